// round 16
// baseline (speedup 1.0000x reference)
#include <cuda_runtime.h>
#include <math.h>

// Problem shape (fixed by the dataset): xyz1 (16,2048,3), xyz2 (16,2048,3)
#define BB 16
#define NN 2048
#define MM 2048
#define RPW 4                 // rows per warp (2 f32x2 pairs)
#define WPB 8                 // warps per block (256 threads)
#define ROWS_PB (RPW * WPB)   // 32 rows per block
#define NCHUNK (MM / 32)      // 64 column chunks

constexpr float EPSv = 1e-9f;

// -------- device scratch (vectors only; NO matrix scratch) ------------------
__device__ float  g_remainL[BB * NN];
__device__ float  g_scaleP[BB * NN];      // scale_i of previous iteration (0 if inactive)
__device__ float  g_rr[2][BB * MM];       // remainR, double-buffered (read k&1, write (k+1)&1)
__device__ float2 g_colacc[3][BB * MM];   // column sums, triple-buffered
__device__ float4 g_xyz1s[BB * NN];       // Morton-sorted row points
__device__ float4 g_xyz2s[BB * MM];       // Morton-sorted column points
__device__ float4 g_cbox[BB * NCHUNK];    // per-column-chunk bounding sphere {cx,cy,cz,R}

typedef unsigned long long u64;

__device__ __forceinline__ float ex2f_neg(float x) {   // 2^(-x)
    float y; asm("{.reg .f32 t; neg.f32 t, %1; ex2.approx.ftz.f32 %0, t;}"
                 : "=f"(y) : "f"(x));
    return y;
}
__device__ __forceinline__ float ex2f(float x) {
    float y; asm("ex2.approx.ftz.f32 %0, %1;" : "=f"(y) : "f"(x)); return y;
}
__device__ __forceinline__ float sqrt_approx(float x) {
    float y; asm("sqrt.approx.ftz.f32 %0, %1;" : "=f"(y) : "f"(x)); return y;
}
__device__ __forceinline__ float rcp_approx(float x) {
    float y; asm("rcp.approx.ftz.f32 %0, %1;" : "=f"(y) : "f"(x)); return y;
}
__device__ __forceinline__ u64 pack2(float lo, float hi) {
    u64 r;
    asm("mov.b64 %0, {%1, %2};" : "=l"(r)
        : "r"(__float_as_uint(lo)), "r"(__float_as_uint(hi)));
    return r;
}
__device__ __forceinline__ void unpack2(u64 v, float& lo, float& hi) {
    unsigned a, b;
    asm("mov.b64 {%0, %1}, %2;" : "=r"(a), "=r"(b) : "l"(v));
    lo = __uint_as_float(a); hi = __uint_as_float(b);
}
__device__ __forceinline__ u64 add2(u64 a, u64 b) {
    u64 r; asm("add.rn.f32x2 %0, %1, %2;" : "=l"(r) : "l"(a), "l"(b)); return r;
}
__device__ __forceinline__ u64 mul2(u64 a, u64 b) {
    u64 r; asm("mul.rn.f32x2 %0, %1, %2;" : "=l"(r) : "l"(a), "l"(b)); return r;
}
__device__ __forceinline__ u64 fma2(u64 a, u64 b, u64 c) {
    u64 r; asm("fma.rn.f32x2 %0, %1, %2, %3;" : "=l"(r) : "l"(a), "l"(b), "l"(c)); return r;
}
__device__ __forceinline__ void red_add_v2(float2* p, float a, float b) {
    asm volatile("red.global.add.v2.f32 [%0], {%1, %2};"
                 :: "l"(p), "f"(a), "f"(b) : "memory");
}
__device__ __forceinline__ unsigned expand10(unsigned v) {
    v &= 0x3FFu;
    v = (v | (v << 16)) & 0x030000FFu;
    v = (v | (v << 8))  & 0x0300F00Fu;
    v = (v | (v << 4))  & 0x030C30C3u;
    v = (v | (v << 2))  & 0x09249249u;
    return v;
}

// ---------------------------------------------------------------------------
__global__ void init_kernel(float* __restrict__ out, float initL, float initR) {
    int idx = blockIdx.x * blockDim.x + threadIdx.x;
    if (idx < BB * NN) { g_remainL[idx] = initL; g_scaleP[idx] = 0.f; }
    if (idx < BB * MM) {
        g_rr[0][idx] = initR; g_rr[1][idx] = initR;
        g_colacc[0][idx] = make_float2(0.f, 0.f);
        g_colacc[1][idx] = make_float2(0.f, 0.f);
        g_colacc[2][idx] = make_float2(0.f, 0.f);
    }
    if (idx < BB) out[idx] = 0.f;
}

// Morton sort (bitonic, 2048 keys in smem) of one side of one batch.
// Writes sorted coords; column side also writes per-32-col bounding spheres.
__global__ void __launch_bounds__(1024) sort_kernel(
    const float* __restrict__ xyz1, const float* __restrict__ xyz2)
{
    const int b = blockIdx.y;
    const int side = blockIdx.x;   // 0: rows (xyz1), 1: cols (xyz2)
    const int N = 2048;
    const float* src = side ? (xyz2 + (size_t)b * MM * 3) : (xyz1 + (size_t)b * NN * 3);
    float4* dst = side ? (g_xyz2s + b * MM) : (g_xyz1s + b * NN);

    __shared__ u64 key[2048];
    const int t = threadIdx.x;
    for (int i = t; i < N; i += 1024) {
        float x = src[3*i], y = src[3*i+1], z = src[3*i+2];
        unsigned ux = (unsigned)fminf(1023.f, fmaxf(0.f, (x + 6.f) * 85.25f));
        unsigned uy = (unsigned)fminf(1023.f, fmaxf(0.f, (y + 6.f) * 85.25f));
        unsigned uz = (unsigned)fminf(1023.f, fmaxf(0.f, (z + 6.f) * 85.25f));
        unsigned code = expand10(ux) | (expand10(uy) << 1) | (expand10(uz) << 2);
        key[i] = ((u64)code << 16) | (unsigned)i;
    }
    __syncthreads();
    for (int kk = 2; kk <= N; kk <<= 1) {
        for (int jj = kk >> 1; jj > 0; jj >>= 1) {
            for (int i = t; i < N; i += 1024) {
                int ixj = i ^ jj;
                if (ixj > i) {
                    u64 a = key[i], c = key[ixj];
                    if (((i & kk) == 0) == (a > c)) { key[i] = c; key[ixj] = a; }
                }
            }
            __syncthreads();
        }
    }
    for (int i = t; i < N; i += 1024) {
        int si = (int)(key[i] & 0xFFFFull);
        dst[i] = make_float4(src[3*si], src[3*si+1], src[3*si+2], 0.f);
    }
    if (side) {
        const int warp = t >> 5, lane = t & 31;
        for (int ch = warp; ch < NCHUNK; ch += 32) {
            int si = (int)(key[ch * 32 + lane] & 0xFFFFull);
            float x = src[3*si], y = src[3*si+1], z = src[3*si+2];
            float mnx = x, mxx = x, mny = y, mxy = y, mnz = z, mxz = z;
#pragma unroll
            for (int off = 16; off > 0; off >>= 1) {
                mnx = fminf(mnx, __shfl_xor_sync(0xffffffffu, mnx, off));
                mxx = fmaxf(mxx, __shfl_xor_sync(0xffffffffu, mxx, off));
                mny = fminf(mny, __shfl_xor_sync(0xffffffffu, mny, off));
                mxy = fmaxf(mxy, __shfl_xor_sync(0xffffffffu, mxy, off));
                mnz = fminf(mnz, __shfl_xor_sync(0xffffffffu, mnz, off));
                mxz = fmaxf(mxz, __shfl_xor_sync(0xffffffffu, mxz, off));
            }
            if (lane == 0) {
                float hx = 0.5f * (mxx - mnx), hy = 0.5f * (mxy - mny), hz = 0.5f * (mxz - mnz);
                g_cbox[b * NCHUNK + ch] = make_float4(
                    0.5f * (mnx + mxx), 0.5f * (mny + mxy), 0.5f * (mnz + mxz),
                    sqrtf(hx*hx + hy*hy + hz*hz));
            }
        }
    }
}

#define MODE_SKIP 1
#define MODE_ZERO 2

// One annealing iteration with the previous iteration's cons FUSED into staging:
// every block recomputes (deterministically, from identical buffered inputs)
//   c = min(rrPrev * rcp(sumr + eps), 1); ccrr = c*rrPrev;
//   rr' = (c<1) ? 0 : max(rrPrev - sumr, 0)
// Block 0 of each batch additionally: writes rr' to the rr write-buffer, zeroes
// the colacc buffer the NEXT iteration will write, and accumulates the cost
// term c*colcost*ccFprev into out[b]. Everything else identical to the
// previous passing kernel (pre-scaled coords, e_old = e_new^4, pruning masks).
template <int MODE>
__global__ void __launch_bounds__(256, 4) passA_kernel(
    float* __restrict__ out,
    float coordScale, float l2old, float sqrtThrN, float sqrtThrO,
    int rdC, int wrC, int zrC, int rdR, int wrR, float ccFprev)
{
    __shared__ float4 sm_pt4[MM];        // {sc*x, sc*y, sc*z, remainR}
    __shared__ float  sm_cr[MM];         // ccrr
    __shared__ float4 sm_cbox[NCHUNK];
    __shared__ unsigned char sm_aRR[NCHUNK], sm_aCR[NCHUNK];
    __shared__ float sm_rsum[WPB];
    __shared__ float sm_cost[WPB];

    const int b = blockIdx.y;
    const int t = threadIdx.x, warp = t >> 5, lane = t & 31;
    const int row0 = blockIdx.x * ROWS_PB + warp * RPW;
    const int brow0 = blockIdx.x * ROWS_PB;
    const bool isB0 = (blockIdx.x == 0);

    // ---- block-wide early exit (block 0 always stages: it owns cons duties) -
    int drained = 1;
    if (t < ROWS_PB) drained = (g_remainL[b * NN + brow0 + t] == 0.f);
    const bool blockDrained = __syncthreads_and(drained);
    if (blockDrained && !isB0) return;

    // ---- staging: fused cons + scaled column data + chunk activity masks ----
    float rsum = 0.f, costL = 0.f;
#pragma unroll
    for (int k = 0; k < 8; k++) {
        const int idx = t + 256 * k;
        float4 p = g_xyz2s[b * MM + idx];
        float2 acc = g_colacc[rdC][b * MM + idx];
        float rrP = g_rr[rdR][b * MM + idx];
        float c = fminf(rrP * rcp_approx(acc.x + EPSv), 1.f);
        float crv = c * rrP;
        float rrv = (c < 1.f) ? 0.f : fmaxf(rrP - acc.x, 0.f);
        p.x *= coordScale; p.y *= coordScale; p.z *= coordScale;
        p.w = rrv;
        sm_pt4[idx] = p;
        sm_cr[idx] = crv;
        rsum += rrv;
        if (isB0) {
            g_rr[wrR][b * MM + idx] = rrv;
            g_colacc[zrC][b * MM + idx] = make_float2(0.f, 0.f);
            costL = fmaf(c, acc.y, costL);
        }
        unsigned mr = __ballot_sync(0xffffffffu, rrv != 0.f);
        unsigned mc = __ballot_sync(0xffffffffu, crv != 0.f);
        if (lane == 0) {
            sm_aRR[warp + 8 * k] = (mr != 0u);
            sm_aCR[warp + 8 * k] = (mc != 0u);
        }
    }
    if (isB0) {
#pragma unroll
        for (int off = 16; off > 0; off >>= 1)
            costL += __shfl_xor_sync(0xffffffffu, costL, off);
        if (lane == 0) sm_cost[warp] = costL;
    }
    if (MODE == MODE_ZERO) {
#pragma unroll
        for (int off = 16; off > 0; off >>= 1)
            rsum += __shfl_xor_sync(0xffffffffu, rsum, off);
        if (lane == 0) sm_rsum[warp] = rsum;
    }
    if (t < NCHUNK) sm_cbox[t] = g_cbox[b * NCHUNK + t];
    __syncthreads();

    if (isB0 && t == 0) {
        float s = 0.f;
#pragma unroll
        for (int w = 0; w < WPB; w++) s += sm_cost[w];
        atomicAdd(&out[b], s * ccFprev);
    }
    if (blockDrained) return;

    // ---- row state; warp exit if all rows drained ----------------------------
    float remL[RPW], scP[RPW];
    bool hasPrev = false, allZero = true;
#pragma unroll
    for (int r = 0; r < RPW; r++) {
        remL[r] = g_remainL[b * NN + row0 + r];
        scP[r]  = g_scaleP[b * NN + row0 + r];
        if (scP[r] != 0.f) hasPrev = true;
        if (remL[r] != 0.f) allZero = false;
    }
    if (allZero) return;   // scaleP already 0 for these rows

    float4 rp0 = g_xyz1s[b * NN + row0 + 0];
    float4 rp1 = g_xyz1s[b * NN + row0 + 1];
    float4 rp2 = g_xyz1s[b * NN + row0 + 2];
    float4 rp3 = g_xyz1s[b * NN + row0 + 3];
    const float cs = coordScale;
    const u64 nx01 = pack2(-cs*rp0.x, -cs*rp1.x), nx23 = pack2(-cs*rp2.x, -cs*rp3.x);
    const u64 ny01 = pack2(-cs*rp0.y, -cs*rp1.y), ny23 = pack2(-cs*rp2.y, -cs*rp3.y);
    const u64 nz01 = pack2(-cs*rp0.z, -cs*rp1.z), nz23 = pack2(-cs*rp2.z, -cs*rp3.z);
    const u64 l2o2 = pack2(l2old, l2old);

    // ---- chunk masks: saturation + bounding spheres (original space) --------
    u64 cRR, cCR;
    {
        unsigned lo = __ballot_sync(0xffffffffu, sm_aRR[lane] != 0);
        unsigned hi = __ballot_sync(0xffffffffu, sm_aRR[32 + lane] != 0);
        cRR = ((u64)hi << 32) | lo;
        lo = __ballot_sync(0xffffffffu, sm_aCR[lane] != 0);
        hi = __ballot_sync(0xffffffffu, sm_aCR[32 + lane] != 0);
        cCR = ((u64)hi << 32) | lo;
    }

    u64 boxN = ~0ull, boxO = ~0ull;
    const bool useN = (MODE != MODE_ZERO) && (sqrtThrN < 8.f);
    const bool useO = hasPrev && (sqrtThrO < 8.f);
    if (useN || useO) {
        float mnx = fminf(fminf(rp0.x, rp1.x), fminf(rp2.x, rp3.x));
        float mxx = fmaxf(fmaxf(rp0.x, rp1.x), fmaxf(rp2.x, rp3.x));
        float mny = fminf(fminf(rp0.y, rp1.y), fminf(rp2.y, rp3.y));
        float mxy = fmaxf(fmaxf(rp0.y, rp1.y), fmaxf(rp2.y, rp3.y));
        float mnz = fminf(fminf(rp0.z, rp1.z), fminf(rp2.z, rp3.z));
        float mxz = fmaxf(fmaxf(rp0.z, rp1.z), fmaxf(rp2.z, rp3.z));
        float rcx = 0.5f * (mnx + mxx), hx = 0.5f * (mxx - mnx);
        float rcy = 0.5f * (mny + mxy), hy = 0.5f * (mxy - mny);
        float rcz = 0.5f * (mnz + mxz), hz = 0.5f * (mxz - mnz);
        float Rrow = sqrt_approx(hx*hx + hy*hy + hz*hz) + 0.02f;

        float4 cb = sm_cbox[lane];
        float dx = rcx - cb.x, dy = rcy - cb.y, dz = rcz - cb.z;
        float d2a = dx*dx + dy*dy + dz*dz;
        float limN = cb.w + Rrow + sqrtThrN, limO = cb.w + Rrow + sqrtThrO;
        unsigned loN = __ballot_sync(0xffffffffu, d2a <= limN * limN);
        unsigned loO = __ballot_sync(0xffffffffu, d2a <= limO * limO);
        cb = sm_cbox[32 + lane];
        dx = rcx - cb.x; dy = rcy - cb.y; dz = rcz - cb.z;
        d2a = dx*dx + dy*dy + dz*dz;
        limN = cb.w + Rrow + sqrtThrN; limO = cb.w + Rrow + sqrtThrO;
        unsigned hiN = __ballot_sync(0xffffffffu, d2a <= limN * limN);
        unsigned hiO = __ballot_sync(0xffffffffu, d2a <= limO * limO);
        if (useN) boxN = ((u64)hiN << 32) | loN;
        if (useO) boxO = ((u64)hiO << 32) | loO;
    }

    const u64 maskS = (MODE == MODE_ZERO) ? 0ull : (cRR & boxN);
    const u64 maskR = hasPrev ? (cCR & boxO) : 0ull;
    const u64 maskAny = maskS | maskR;

    u64 srow01 = 0ull, srow23 = 0ull, rdp01 = 0ull, rdp23 = 0ull;  // (0.f,0.f)
    u64 aliveMask = 0ull;

    // ---- loop 1: new-level row sums + old-level deferred decrement ----------
    for (int c = 0; c < MM; c += 32) {
        const int ch = c >> 5;
        if (!((maskAny >> ch) & 1ull)) continue;

        const int col = c + lane;
        const float4 pt = sm_pt4[col];
        const u64 bx2 = pack2(pt.x, pt.x);
        const u64 by2 = pack2(pt.y, pt.y);
        const u64 bz2 = pack2(pt.z, pt.z);

        u64 r201, r223;   // scaled squared distances == negated exp args
        {
            u64 dx = add2(bx2, nx01), dy = add2(by2, ny01), dz = add2(bz2, nz01);
            r201 = fma2(dz, dz, fma2(dy, dy, mul2(dx, dx)));
            dx = add2(bx2, nx23); dy = add2(by2, ny23); dz = add2(bz2, nz23);
            r223 = fma2(dz, dz, fma2(dy, dy, mul2(dx, dx)));
        }

        if (MODE == MODE_ZERO) {
            float b0, b1, b2, b3;
            unpack2(mul2(r201, l2o2), b0, b1);
            unpack2(mul2(r223, l2o2), b2, b3);
            const u64 e01 = pack2(ex2f(b0), ex2f(b1));
            const u64 e23 = pack2(ex2f(b2), ex2f(b3));
            const float lcr = sm_cr[col];
            const u64 lcr2 = pack2(lcr, lcr);
            rdp01 = fma2(e01, lcr2, rdp01);
            rdp23 = fma2(e23, lcr2, rdp23);
        } else {
            const bool bS = (maskS >> ch) & 1ull;
            const bool bR = (maskR >> ch) & 1ull;
            float a0, a1, a2, a3;
            unpack2(r201, a0, a1);
            unpack2(r223, a2, a3);
            float amin = fminf(fminf(a0, a1), fminf(a2, a3));
            const float vthr = bS ? 126.f : 31.5f;   // old arg = 4*new arg
            if (__any_sync(0xffffffffu, amin < vthr)) {
                const u64 e01 = pack2(ex2f_neg(a0), ex2f_neg(a1));
                const u64 e23 = pack2(ex2f_neg(a2), ex2f_neg(a3));
                if (bS) {
                    aliveMask |= 1ull << ch;
                    const u64 lrr2 = pack2(pt.w, pt.w);
                    srow01 = fma2(e01, lrr2, srow01);
                    srow23 = fma2(e23, lrr2, srow23);
                }
                if (bR) {
                    const float lcr = sm_cr[col];
                    const u64 lcr2 = pack2(lcr, lcr);
                    u64 q01 = mul2(e01, e01); q01 = mul2(q01, q01);
                    u64 q23 = mul2(e23, e23); q23 = mul2(q23, q23);
                    rdp01 = fma2(q01, lcr2, rdp01);
                    rdp23 = fma2(q23, lcr2, rdp23);
                }
            }
        }
    }

    float srow[RPW], rdp[RPW];
    unpack2(srow01, srow[0], srow[1]);
    unpack2(srow23, srow[2], srow[3]);
    unpack2(rdp01, rdp[0], rdp[1]);
    unpack2(rdp23, rdp[2], rdp[3]);

    // ---- warp-only reduction -------------------------------------------------
#pragma unroll
    for (int off = 16; off > 0; off >>= 1) {
#pragma unroll
        for (int r = 0; r < RPW; r++) {
            rdp[r] += __shfl_xor_sync(0xffffffffu, rdp[r], off);
            if (MODE != MODE_ZERO)
                srow[r] += __shfl_xor_sync(0xffffffffu, srow[r], off);
        }
    }
    if (MODE == MODE_ZERO) {
        float raccT = 0.f;
#pragma unroll
        for (int w = 0; w < WPB; w++) raccT += sm_rsum[w];
#pragma unroll
        for (int r = 0; r < RPW; r++) srow[r] = raccT;
    }

    float scaleEff[RPW];
    bool anyAct = false;
#pragma unroll
    for (int r = 0; r < RPW; r++) {
        const int li = b * NN + row0 + r;
        float rl = fmaxf(remL[r] - scP[r] * rdp[r], 0.f);
        if (rl < 1e-6f) rl = 0.f;          // drained row -> exact zero
        float sc = rl / (srow[r] + EPSv);
        const bool act = (srow[r] != 0.f) && (rl != 0.f);
        scaleEff[r] = act ? sc : 0.f;
        if (act) anyAct = true;
        if (lane == 0) {
            g_remainL[li] = rl;
            g_scaleP[li] = act ? sc : 0.f;
        }
    }

    if (!anyAct) return;

    const u64 sc01 = pack2(scaleEff[0], scaleEff[1]);
    const u64 sc23 = pack2(scaleEff[2], scaleEff[3]);
    const u64 ONE2 = pack2(1.f, 1.f);
    const u64 mask2 = (MODE == MODE_ZERO) ? cRR : aliveMask;

    // ---- loop 2: recompute e (bit-identical), scale, column partials --------
    for (int c = 0; c < MM; c += 32) {
        if (!((mask2 >> (c >> 5)) & 1ull)) continue;

        const int col = c + lane;
        const float4 pt = sm_pt4[col];
        const u64 bx2 = pack2(pt.x, pt.x);
        const u64 by2 = pack2(pt.y, pt.y);
        const u64 bz2 = pack2(pt.z, pt.z);

        u64 r201, r223;
        {
            u64 dx = add2(bx2, nx01), dy = add2(by2, ny01), dz = add2(bz2, nz01);
            r201 = fma2(dz, dz, fma2(dy, dy, mul2(dx, dx)));
            dx = add2(bx2, nx23); dy = add2(by2, ny23); dz = add2(bz2, nz23);
            r223 = fma2(dz, dz, fma2(dy, dy, mul2(dx, dx)));
        }

        float a0, a1, a2, a3;
        unpack2(r201, a0, a1);
        unpack2(r223, a2, a3);

        u64 e01, e23;
        if (MODE == MODE_ZERO) {
            e01 = ONE2; e23 = ONE2;
        } else {
            e01 = pack2(ex2f_neg(a0), ex2f_neg(a1));
            e23 = pack2(ex2f_neg(a2), ex2f_neg(a3));
        }

        const u64 lrr2 = pack2(pt.w, pt.w);
        const u64 w01 = mul2(mul2(e01, lrr2), sc01);
        const u64 w23 = mul2(mul2(e23, lrr2), sc23);

        float wl, wh;
        unpack2(add2(w01, w23), wl, wh);
        const float csum = wl + wh;

        const u64 s01 = pack2(sqrt_approx(a0), sqrt_approx(a1));
        const u64 s23 = pack2(sqrt_approx(a2), sqrt_approx(a3));

        float cl, ch2;
        unpack2(fma2(w23, s23, mul2(w01, s01)), cl, ch2);
        const float ccost = cl + ch2;

        red_add_v2(&g_colacc[wrC][b * MM + col], csum, ccost);
    }
}

// Final cost flush: process the LAST iteration's colacc (no state updates).
__global__ void __launch_bounds__(256) final_cost_kernel(
    float* __restrict__ out, int rdC, int rdR, float ccF)
{
    const int b = blockIdx.y;
    const int l = blockIdx.x * 256 + threadIdx.x;
    const int idx = b * MM + l;

    float2 acc = g_colacc[rdC][idx];
    float rrv = g_rr[rdR][idx];
    float c = fminf(rrv * rcp_approx(acc.x + EPSv), 1.0f);
    float local = c * acc.y * ccF;

#pragma unroll
    for (int off = 16; off > 0; off >>= 1)
        local += __shfl_xor_sync(0xffffffffu, local, off);

    __shared__ float red[8];
    const int warp = threadIdx.x >> 5, lane = threadIdx.x & 31;
    if (lane == 0) red[warp] = local;
    __syncthreads();
    if (threadIdx.x == 0) {
        float s = 0.f;
#pragma unroll
        for (int w = 0; w < 8; w++) s += red[w];
        atomicAdd(&out[b], s);
    }
}

// ---------------------------------------------------------------------------
extern "C" void kernel_launch(void* const* d_in, const int* in_sizes, int n_in,
                              void* d_out, int out_size) {
    (void)in_sizes; (void)n_in; (void)out_size;
    const float* xyz1 = (const float*)d_in[0];
    const float* xyz2 = (const float*)d_in[1];
    float* out = (float*)d_out;

    const float mx = (float)(NN > MM ? NN : MM);
    init_kernel<<<(BB * MM + 255) / 256, 256>>>(out, mx / (float)NN, mx / (float)MM);
    sort_kernel<<<dim3(2, BB), 1024>>>(xyz1, xyz2);

    const float LOG2E = 1.4426950408889634f;
    dim3 grid(NN / ROWS_PB, BB);     // (64, 16) = 1024 blocks
    dim3 fgrid(MM / 256, BB);        // (8, 16) = 128 blocks

    float l2old = 0.f;
    float ccFprev = 1.0f;
    int k = 0;
    for (int j = 7; j >= -2; --j, ++k) {
        float level = (j == -2) ? 0.f : -powf(4.f, (float)j);
        float l2new = level * LOG2E;

        const int rdC = k % 3, wrC = (k + 1) % 3, zrC = (k + 2) % 3;
        const int rdR = k & 1, wrR = (k + 1) & 1;

        if (j == -2) {
            passA_kernel<MODE_ZERO><<<grid, 256>>>(
                out, 1.0f, l2old, 1e9f, 1e9f, rdC, wrC, zrC, rdR, wrR, ccFprev);
            ccFprev = 1.0f;
        } else {
            float coordScale = sqrtf(-l2new);
            float sqrtThrN = sqrtf(126.f / (-l2new));
            float sqrtThrO = sqrtThrN * 0.5f;   // l2old == 4*l2new
            passA_kernel<MODE_SKIP><<<grid, 256>>>(
                out, coordScale, l2old, sqrtThrN, sqrtThrO,
                rdC, wrC, zrC, rdR, wrR, ccFprev);
            ccFprev = 1.0f / coordScale;
        }

        l2old = l2new;
    }
    // flush the last iteration's cost (k == 10 here)
    final_cost_kernel<<<fgrid, 256>>>(out, k % 3, k & 1, ccFprev);
}